// round 7
// baseline (speedup 1.0000x reference)
#include <cuda_runtime.h>

typedef unsigned long long u64;

#define H_      51
#define TSTEPS  512
#define BTOT    1024
#define NB      8                 // batch rows per block
#define NBLK    (BTOT / NB)       // 128 blocks
#define NTHR    512
#define GP_     224               // padded gate count (204 -> 224 = 7*32)
#define L1K4    13                // layer1 K: 52 -> 13 float4 chunks
#define L2K4    26                // layer2 K: 104 -> 26 float4 chunks
#define HROW    108               // h row: [h1(51)|pad|h2(51)|pad..]
#define HC      (HROW/4)          // 27 ulonglong2 per h row
#define PR1     228               // partial row stride per batch (floats)
#define PR2     (NB * PR1)        // per-level partial block (1824)
#define L1KH    3                 // layer1 k-levels
#define L2KH    5                 // layer2 k-levels

// gate packing: NEW gate index g (0..203): unit u = g>>2, q = g&3 (i,f,g,o)
// -> original row = q*51 + u. Unit u's 4 gates are contiguous (float4).

// ---- shared memory layout (float offsets) ----
#define OFF_W1   0                          // [13][224][4]
#define OFF_W2   (OFF_W1 + L1K4*GP_*4)      // [26][224][4]
#define OFF_XS   (OFF_W2 + L2K4*GP_*4)      // [512][8]
#define OFF_HS   (OFF_XS + TSTEPS*NB)       // [8][108]
#define OFF_C1   (OFF_HS + NB*HROW)         // [8][52]
#define OFF_C2   (OFF_C1 + NB*52)           // [8][52]
#define OFF_PB   (OFF_C2 + NB*52)           // [8 levels][8 b][228]
#define OFF_PB2  (OFF_PB + L1KH*PR2)
#define OFF_B1   (OFF_PB + 8*PR2)           // 224
#define OFF_B2   (OFF_B1 + GP_)             // 224
#define OFF_WI1  (OFF_B2 + GP_)             // 224
#define OFF_WL   (OFF_WI1 + GP_)            // 52
#define OFF_BL   (OFF_WL + 52)              // 4
#define SMEM_FLOATS (OFF_BL + 4)
#define SMEM_BYTES  (SMEM_FLOATS * 4)       // ~224.5 KB

__device__ __forceinline__ void ffma2(u64 &d, u64 a, u64 b) {
    asm("fma.rn.f32x2 %0, %1, %2, %0;" : "+l"(d) : "l"(a), "l"(b));
}
__device__ __forceinline__ float2 unpk(u64 v) {
    float2 r;
    asm("mov.b64 {%0, %1}, %2;" : "=f"(r.x), "=f"(r.y) : "l"(v));
    return r;
}
__device__ __forceinline__ float sigf(float x) {
    return __fdividef(1.0f, 1.0f + __expf(-x));
}
__device__ __forceinline__ float tanhfast(float x) {
    return __fdividef(2.0f, 1.0f + __expf(-2.0f * x)) - 1.0f;
}

// gate GEMV: warp covers NJ gate-groups x ALL 8 batches over NKQ k-chunks.
// Batches processed in halves of 4 to cap live registers.
template<int NKQ, int NJ>
__device__ __forceinline__ void gate_gemv(const ulonglong2* __restrict__ wp,
                                          const ulonglong2* __restrict__ hp,
                                          u64 (&acc)[NJ][8])
{
#pragma unroll
    for (int j = 0; j < NJ; j++)
#pragma unroll
        for (int b = 0; b < 8; b++) acc[j][b] = 0ull;
#pragma unroll
    for (int i = 0; i < NKQ; i++) {
        ulonglong2 w[NJ];
#pragma unroll
        for (int j = 0; j < NJ; j++) w[j] = wp[i * GP_ + 32 * j];
#pragma unroll
        for (int half = 0; half < 2; half++) {
            ulonglong2 h[4];
#pragma unroll
            for (int b = 0; b < 4; b++) h[b] = hp[(half * 4 + b) * HC + i];
#pragma unroll
            for (int j = 0; j < NJ; j++)
#pragma unroll
                for (int b = 0; b < 4; b++) {
                    ffma2(acc[j][half * 4 + b], w[j].x, h[b].x);
                    ffma2(acc[j][half * 4 + b], w[j].y, h[b].y);
                }
        }
    }
}

// write per-level partial sums; ADDX folds in the x * W_ih1 term
template<int NJ, bool ADDX>
__device__ __forceinline__ void store_partial(float* __restrict__ pb,
                                              const float* __restrict__ wiP,
                                              u64 (&acc)[NJ][8],
                                              const float* __restrict__ xrow)
{
    float wi[NJ];
    if (ADDX) {
#pragma unroll
        for (int j = 0; j < NJ; j++) wi[j] = wiP[32 * j];
    }
#pragma unroll
    for (int b = 0; b < 8; b++) {
        float xv = ADDX ? xrow[b] : 0.0f;
#pragma unroll
        for (int j = 0; j < NJ; j++) {
            float2 p = unpk(acc[j][b]);
            float gv = p.x + p.y;
            if (ADDX) gv = fmaf(xv, wi[j], gv);
            pb[b * PR1 + 32 * j] = gv;
        }
    }
}

// pointwise cell update: thread (b = tid>>6, u = tid&63, active u<51).
// Gates packed (u,q) -> one float4 per level, one float4 bias.
template<int NLEV>
__device__ __forceinline__ void update_phase(float* sm, int b, int u, bool act,
                                             int coff, int hoff, int boff,
                                             int pboff)
{
    if (act) {
        const float4* pb = (const float4*)(sm + pboff + b * PR1 + 4 * u);
        float4 bias = *(const float4*)(sm + boff + 4 * u);
        float gi = bias.x, gf = bias.y, gg = bias.z, go = bias.w;
#pragma unroll
        for (int l = 0; l < NLEV; l++) {
            float4 p = pb[l * (PR2 / 4)];
            gi += p.x; gf += p.y; gg += p.z; go += p.w;
        }
        float c  = sm[coff + b * 52 + u];
        float cn = sigf(gf) * c + sigf(gi) * tanhfast(gg);
        float hn = sigf(go) * tanhfast(cn);
        sm[coff + b * 52 + u] = cn;
        sm[OFF_HS + b * HROW + hoff + u] = hn;
    }
}

__device__ __forceinline__ void out_phase(const float* sm, int lane, int bid,
                                          int tcol, float* __restrict__ out)
{
    int ob = lane & 7, part = lane >> 3;            // 4 parts x 13 k
    float a = 0.0f;
#pragma unroll
    for (int kk = 0; kk < 13; kk++) {
        int k = part * 13 + kk;                     // k max 51 -> zero pad
        a = fmaf(sm[OFF_HS + ob * HROW + 52 + k], sm[OFF_WL + k], a);
    }
    a += __shfl_xor_sync(0xffffffffu, a, 8);
    a += __shfl_xor_sync(0xffffffffu, a, 16);
    if (lane < 8)
        out[(bid * NB + ob) * TSTEPS + tcol] = a + sm[OFF_BL];
}

__global__ void __launch_bounds__(NTHR, 1)
lstm_kernel(const float* __restrict__ input,
            const float* __restrict__ Wih1, const float* __restrict__ Whh1,
            const float* __restrict__ bih1, const float* __restrict__ bhh1,
            const float* __restrict__ Wih2, const float* __restrict__ Whh2,
            const float* __restrict__ bih2, const float* __restrict__ bhh2,
            const float* __restrict__ Wlin, const float* __restrict__ blin,
            float* __restrict__ out)
{
    extern __shared__ float sm[];
    const int tid  = threadIdx.x;
    const int bid  = blockIdx.x;
    const int lane = tid & 31;
    const int wid  = tid >> 5;            // 0..15

    // ---- staging (gate index permuted: og = (g&3)*51 + (g>>2)) ----
    for (int i = tid; i < NB * HROW; i += NTHR) sm[OFF_HS + i] = 0.0f;
    for (int i = tid; i < NB * 52 * 2; i += NTHR) sm[OFF_C1 + i] = 0.0f;

    for (int i = tid; i < TSTEPS * NB; i += NTHR) {
        int t = i >> 3, bb = i & 7;
        sm[OFF_XS + i] = input[t * BTOT + bid * NB + bb];
    }
    for (int i = tid; i < L1K4 * GP_ * 4; i += NTHR) {
        int c = i & 3, g = (i >> 2) % GP_, kq = i / (GP_ * 4);
        int k = 4 * kq + c;
        float v = 0.0f;
        if (g < 204 && k < H_) {
            int og = (g & 3) * 51 + (g >> 2);
            v = Whh1[og * H_ + k];
        }
        sm[OFF_W1 + i] = v;
    }
    for (int i = tid; i < L2K4 * GP_ * 4; i += NTHR) {
        int c = i & 3, g = (i >> 2) % GP_, kq = i / (GP_ * 4);
        int k = 4 * kq + c;
        float v = 0.0f;
        if (g < 204) {
            int og = (g & 3) * 51 + (g >> 2);
            if (k < H_)                  v = Wih2[og * H_ + k];
            else if (k >= 52 && k < 103) v = Whh2[og * H_ + (k - 52)];
        }
        sm[OFF_W2 + i] = v;
    }
    for (int i = tid; i < GP_; i += NTHR) {
        float b1 = 0.0f, b2 = 0.0f, w1 = 0.0f;
        if (i < 204) {
            int og = (i & 3) * 51 + (i >> 2);
            b1 = bih1[og] + bhh1[og];
            b2 = bih2[og] + bhh2[og];
            w1 = Wih1[og];
        }
        sm[OFF_B1  + i] = b1;
        sm[OFF_B2  + i] = b2;
        sm[OFF_WI1 + i] = w1;
    }
    if (tid < 52) sm[OFF_WL + tid] = (tid < H_) ? Wlin[tid] : 0.0f;
    if (tid == 0) sm[OFF_BL] = blin[0];
    __syncthreads();

    // warp roles: wid 0..5 = L1 (kh = wid>>1 in 0..2, jh = wid&1)
    //             wid 6..15 = L2 (kh = (wid-6)>>1 in 0..4, jh = (wid-6)&1)
    // jh=0 -> gate-groups j 0..3 (NJ=4), jh=1 -> j 4..6 (NJ=3)
    const bool isL1 = (wid < 6);
    const int  sub  = isL1 ? wid : wid - 6;
    const int  kh   = sub >> 1;
    const int  jh   = sub & 1;
    const int  jbase = jh ? 4 : 0;

    const int l1start[4] = {0, 5, 9, 13};
    const int l2start[6] = {0, 6, 11, 16, 21, 26};
    const int kstart = isL1 ? l1start[kh] : l2start[kh];

    const ulonglong2* __restrict__ wp =
        reinterpret_cast<const ulonglong2*>(sm + (isL1 ? OFF_W1 : OFF_W2))
        + kstart * GP_ + lane + 32 * jbase;
    const ulonglong2* __restrict__ hp =
        reinterpret_cast<const ulonglong2*>(sm + OFF_HS) + kstart;
    float* pb = sm + (isL1 ? OFF_PB : OFF_PB2) + kh * PR2 + lane + 32 * jbase;
    const float* wiP = sm + OFF_WI1 + lane + 32 * jbase;

    const int ub = tid >> 6;              // update batch 0..7
    const int uu = tid & 63;              // update unit
    const bool uact = (uu < H_);

    // L1 gate work for one step (needs h1 of previous step + x of this step)
    auto do_l1 = [&](const float* xrow) {
        if (jh == 0) {
            u64 acc[4][8];
            if (kh == 0) {
                gate_gemv<5, 4>(wp, hp, acc);
                store_partial<4, true>(pb, wiP, acc, xrow);
            } else if (kh == 1) {
                gate_gemv<4, 4>(wp, hp, acc);
                store_partial<4, false>(pb, wiP, acc, xrow);
            } else {
                gate_gemv<4, 4>(wp, hp, acc);
                store_partial<4, false>(pb, wiP, acc, xrow);
            }
        } else {
            u64 acc[3][8];
            if (kh == 0) {
                gate_gemv<5, 3>(wp, hp, acc);
                store_partial<3, true>(pb, wiP, acc, xrow);
            } else if (kh == 1) {
                gate_gemv<4, 3>(wp, hp, acc);
                store_partial<3, false>(pb, wiP, acc, xrow);
            } else {
                gate_gemv<4, 3>(wp, hp, acc);
                store_partial<3, false>(pb, wiP, acc, xrow);
            }
        }
    };
    auto do_l2 = [&]() {
        if (jh == 0) {
            u64 acc[4][8];
            if (kh == 0) gate_gemv<6, 4>(wp, hp, acc);
            else         gate_gemv<5, 4>(wp, hp, acc);
            store_partial<4, false>(pb, nullptr, acc, nullptr);
        } else {
            u64 acc[3][8];
            if (kh == 0) gate_gemv<6, 3>(wp, hp, acc);
            else         gate_gemv<5, 3>(wp, hp, acc);
            store_partial<3, false>(pb, nullptr, acc, nullptr);
        }
    };

    // ---- prologue: G1(0), U1(0) ----
    if (isL1) do_l1(sm + OFF_XS + 0 * NB);
    __syncthreads();
    update_phase<L1KH>(sm, ub, uu, uact, OFF_C1, 0, OFF_B1, OFF_PB);
    __syncthreads();

    // ---- pipelined recurrence ----
    for (int t = 0; t < TSTEPS; t++) {
        // phase A: G2(t) on L2 warps; G1(t+1) on L1 warps; out(t-1) on warp 5
        if (isL1) {
            if (t + 1 < TSTEPS) do_l1(sm + OFF_XS + (t + 1) * NB);
            if (wid == 5 && t > 0) out_phase(sm, lane, bid, t - 1, out);
        } else {
            do_l2();
        }
        __syncthreads();

        // phase B: U2(t) then U1(t+1)
        update_phase<L2KH>(sm, ub, uu, uact, OFF_C2, 52, OFF_B2, OFF_PB2);
        if (t + 1 < TSTEPS)
            update_phase<L1KH>(sm, ub, uu, uact, OFF_C1, 0, OFF_B1, OFF_PB);
        __syncthreads();
    }

    // ---- epilogue: out(511) ----
    if (wid == 5) out_phase(sm, lane, bid, TSTEPS - 1, out);
}

extern "C" void kernel_launch(void* const* d_in, const int* in_sizes, int n_in,
                              void* d_out, int out_size)
{
    const float* input = (const float*)d_in[0];
    const float* Wih1  = (const float*)d_in[1];
    const float* Whh1  = (const float*)d_in[2];
    const float* bih1  = (const float*)d_in[3];
    const float* bhh1  = (const float*)d_in[4];
    const float* Wih2  = (const float*)d_in[5];
    const float* Whh2  = (const float*)d_in[6];
    const float* bih2  = (const float*)d_in[7];
    const float* bhh2  = (const float*)d_in[8];
    const float* Wlin  = (const float*)d_in[9];
    const float* blin  = (const float*)d_in[10];
    float* out = (float*)d_out;

    static bool attr_set = false;
    if (!attr_set) {
        cudaFuncSetAttribute(lstm_kernel,
                             cudaFuncAttributeMaxDynamicSharedMemorySize,
                             SMEM_BYTES);
        attr_set = true;
    }
    lstm_kernel<<<NBLK, NTHR, SMEM_BYTES>>>(input, Wih1, Whh1, bih1, bhh1,
                                            Wih2, Whh2, bih2, bhh2,
                                            Wlin, blin, out);
}

// round 8
// speedup vs baseline: 1.6730x; 1.6730x over previous
#include <cuda_runtime.h>

typedef unsigned long long u64;

#define H_      51
#define TSTEPS  512
#define BTOT    1024
#define NB      8                 // batch rows per block
#define NBLK    (BTOT / NB)       // 128 blocks
#define NTHR    512
#define GP_     224               // padded gate count (204 -> 224 = 7*32)
#define L1K4    13                // layer1 K: 52 -> 13 float4 chunks
#define L2K4    26                // layer2 K: 104 -> 26 float4 chunks
#define HROW    108               // h row: [h1(51)|pad|h2(51)|pad..]
#define HC      (HROW/4)          // 27 ulonglong2 per h row
#define PR1     228               // partial row stride per batch (floats, 912B = 57*16)
#define PR2     (NB * PR1)        // per-level partial block (1824)
#define L1KH    3                 // layer1 k-levels
#define L2KH    5                 // layer2 k-levels

// gate packing: NEW gate index g (0..203): unit u = g>>2, q = g&3 (i,f,g,o)
// original row og = q*51 + u. Unit u's 4 gates are contiguous -> float4 reads.

// ---- shared memory layout (float offsets) ----
#define OFF_W1   0                          // [13][224][4]
#define OFF_W2   (OFF_W1 + L1K4*GP_*4)      // [26][224][4]
#define OFF_XS   (OFF_W2 + L2K4*GP_*4)      // [512][8]
#define OFF_HS   (OFF_XS + TSTEPS*NB)       // [8][108]
#define OFF_C1   (OFF_HS + NB*HROW)         // [8][52]
#define OFF_C2   (OFF_C1 + NB*52)           // [8][52]
#define OFF_PB   (OFF_C2 + NB*52)           // [8 levels][8 b][228]: 3 L1 + 5 L2
#define OFF_PB2  (OFF_PB + L1KH*PR2)
#define OFF_B1   (OFF_PB + 8*PR2)           // 224 (16B aligned)
#define OFF_B2   (OFF_B1 + GP_)             // 224
#define OFF_WI1  (OFF_B2 + GP_)             // 224
#define OFF_WL   (OFF_WI1 + GP_)            // 52
#define OFF_BL   (OFF_WL + 52)              // 4
#define SMEM_FLOATS (OFF_BL + 4)
#define SMEM_BYTES  (SMEM_FLOATS * 4)       // ~224.5 KB

__device__ __forceinline__ void ffma2(u64 &d, u64 a, u64 b) {
    asm("fma.rn.f32x2 %0, %1, %2, %0;" : "+l"(d) : "l"(a), "l"(b));
}
__device__ __forceinline__ float2 unpk(u64 v) {
    float2 r;
    asm("mov.b64 {%0, %1}, %2;" : "=f"(r.x), "=f"(r.y) : "l"(v));
    return r;
}
__device__ __forceinline__ float sigf(float x) {
    return __fdividef(1.0f, 1.0f + __expf(-x));
}
__device__ __forceinline__ float tanhfast(float x) {
    return __fdividef(2.0f, 1.0f + __expf(-2.0f * x)) - 1.0f;
}

// gate GEMV over NKQ static k-chunks: lane = gate slot (g = lane + 32j),
// warp covers batches bh*4..bh*4+3. (R6-proven register shape.)
template<int NKQ>
__device__ __forceinline__ void gate_gemv(const ulonglong2* __restrict__ wp,
                                          const ulonglong2* __restrict__ hp,
                                          u64 (&acc)[7][4])
{
#pragma unroll
    for (int j = 0; j < 7; j++)
#pragma unroll
        for (int b = 0; b < 4; b++) acc[j][b] = 0ull;
#pragma unroll
    for (int i = 0; i < NKQ; i++) {
        ulonglong2 h[4];
#pragma unroll
        for (int b = 0; b < 4; b++) h[b] = hp[b * HC + i];
#pragma unroll
        for (int j = 0; j < 7; j++) {
            ulonglong2 w = wp[i * GP_ + 32 * j];
#pragma unroll
            for (int b = 0; b < 4; b++) {
                ffma2(acc[j][b], w.x, h[b].x);
                ffma2(acc[j][b], w.y, h[b].y);
            }
        }
    }
}

__device__ __forceinline__ void store_partial(float* __restrict__ pb,
                                              const float* __restrict__ sm,
                                              int lane, int bh,
                                              u64 (&acc)[7][4],
                                              bool addx, const float* xrow)
{
    float wi[7];
    if (addx) {
#pragma unroll
        for (int j = 0; j < 7; j++) wi[j] = sm[OFF_WI1 + lane + 32 * j];
    }
#pragma unroll
    for (int b = 0; b < 4; b++) {
        float xv = addx ? xrow[bh * 4 + b] : 0.0f;
#pragma unroll
        for (int j = 0; j < 7; j++) {
            float2 p = unpk(acc[j][b]);
            float gv = p.x + p.y;
            if (addx) gv = fmaf(xv, wi[j], gv);
            pb[(bh * 4 + b) * PR1 + 32 * j] = gv;
        }
    }
}

// merged pointwise update: U2(t) and U1(t+1) are independent -> one phase,
// two interleaved chains. thread (b = tid>>6, u = tid&63, active u<51).
// float4 gate reads thanks to (u,q) packing.
__device__ __forceinline__ void update_both(float* sm, int b, int u, bool act,
                                            bool doU1)
{
    if (act) {
        const float4* p2 = (const float4*)(sm + OFF_PB2 + b * PR1 + 4 * u);
        float4 bs2 = *(const float4*)(sm + OFF_B2 + 4 * u);
        float gi2 = bs2.x, gf2 = bs2.y, gg2 = bs2.z, go2 = bs2.w;
#pragma unroll
        for (int l = 0; l < L2KH; l++) {
            float4 p = p2[l * (PR2 / 4)];
            gi2 += p.x; gf2 += p.y; gg2 += p.z; go2 += p.w;
        }
        float gi1, gf1, gg1, go1;
        if (doU1) {
            const float4* p1 = (const float4*)(sm + OFF_PB + b * PR1 + 4 * u);
            float4 bs1 = *(const float4*)(sm + OFF_B1 + 4 * u);
            gi1 = bs1.x; gf1 = bs1.y; gg1 = bs1.z; go1 = bs1.w;
#pragma unroll
            for (int l = 0; l < L1KH; l++) {
                float4 p = p1[l * (PR2 / 4)];
                gi1 += p.x; gf1 += p.y; gg1 += p.z; go1 += p.w;
            }
        }
        float c2  = sm[OFF_C2 + b * 52 + u];
        float cn2 = sigf(gf2) * c2 + sigf(gi2) * tanhfast(gg2);
        float hn2 = sigf(go2) * tanhfast(cn2);
        sm[OFF_C2 + b * 52 + u] = cn2;
        sm[OFF_HS + b * HROW + 52 + u] = hn2;
        if (doU1) {
            float c1  = sm[OFF_C1 + b * 52 + u];
            float cn1 = sigf(gf1) * c1 + sigf(gi1) * tanhfast(gg1);
            float hn1 = sigf(go1) * tanhfast(cn1);
            sm[OFF_C1 + b * 52 + u] = cn1;
            sm[OFF_HS + b * HROW + u] = hn1;
        }
    }
}

// U1-only (prologue)
__device__ __forceinline__ void update_l1(float* sm, int b, int u, bool act)
{
    if (act) {
        const float4* p1 = (const float4*)(sm + OFF_PB + b * PR1 + 4 * u);
        float4 bs1 = *(const float4*)(sm + OFF_B1 + 4 * u);
        float gi = bs1.x, gf = bs1.y, gg = bs1.z, go = bs1.w;
#pragma unroll
        for (int l = 0; l < L1KH; l++) {
            float4 p = p1[l * (PR2 / 4)];
            gi += p.x; gf += p.y; gg += p.z; go += p.w;
        }
        float c  = sm[OFF_C1 + b * 52 + u];
        float cn = sigf(gf) * c + sigf(gi) * tanhfast(gg);
        float hn = sigf(go) * tanhfast(cn);
        sm[OFF_C1 + b * 52 + u] = cn;
        sm[OFF_HS + b * HROW + u] = hn;
    }
}

__device__ __forceinline__ void out_phase(const float* sm, int lane, int bid,
                                          int tcol, float* __restrict__ out)
{
    int ob = lane & 7, part = lane >> 3;            // 4 parts x 13 k
    float a = 0.0f;
#pragma unroll
    for (int kk = 0; kk < 13; kk++) {
        int k = part * 13 + kk;                     // k max 51 -> zero pad
        a = fmaf(sm[OFF_HS + ob * HROW + 52 + k], sm[OFF_WL + k], a);
    }
    a += __shfl_xor_sync(0xffffffffu, a, 8);
    a += __shfl_xor_sync(0xffffffffu, a, 16);
    if (lane < 8)
        out[(bid * NB + ob) * TSTEPS + tcol] = a + sm[OFF_BL];
}

__global__ void __launch_bounds__(NTHR, 1)
lstm_kernel(const float* __restrict__ input,
            const float* __restrict__ Wih1, const float* __restrict__ Whh1,
            const float* __restrict__ bih1, const float* __restrict__ bhh1,
            const float* __restrict__ Wih2, const float* __restrict__ Whh2,
            const float* __restrict__ bih2, const float* __restrict__ bhh2,
            const float* __restrict__ Wlin, const float* __restrict__ blin,
            float* __restrict__ out)
{
    extern __shared__ float sm[];
    const int tid  = threadIdx.x;
    const int bid  = blockIdx.x;
    const int lane = tid & 31;
    const int wid  = tid >> 5;            // 0..15

    // ---- staging (gate index permuted: og = (g&3)*51 + (g>>2)) ----
    for (int i = tid; i < NB * HROW; i += NTHR) sm[OFF_HS + i] = 0.0f;
    for (int i = tid; i < NB * 52 * 2; i += NTHR) sm[OFF_C1 + i] = 0.0f;

    for (int i = tid; i < TSTEPS * NB; i += NTHR) {
        int t = i >> 3, bb = i & 7;
        sm[OFF_XS + i] = input[t * BTOT + bid * NB + bb];
    }
    for (int i = tid; i < L1K4 * GP_ * 4; i += NTHR) {
        int c = i & 3, g = (i >> 2) % GP_, kq = i / (GP_ * 4);
        int k = 4 * kq + c;
        float v = 0.0f;
        if (g < 204 && k < H_) {
            int og = (g & 3) * 51 + (g >> 2);
            v = Whh1[og * H_ + k];
        }
        sm[OFF_W1 + i] = v;
    }
    for (int i = tid; i < L2K4 * GP_ * 4; i += NTHR) {
        int c = i & 3, g = (i >> 2) % GP_, kq = i / (GP_ * 4);
        int k = 4 * kq + c;
        float v = 0.0f;
        if (g < 204) {
            int og = (g & 3) * 51 + (g >> 2);
            if (k < H_)                  v = Wih2[og * H_ + k];
            else if (k >= 52 && k < 103) v = Whh2[og * H_ + (k - 52)];
        }
        sm[OFF_W2 + i] = v;
    }
    for (int i = tid; i < GP_; i += NTHR) {
        float b1 = 0.0f, b2 = 0.0f, w1 = 0.0f;
        if (i < 204) {
            int og = (i & 3) * 51 + (i >> 2);
            b1 = bih1[og] + bhh1[og];
            b2 = bih2[og] + bhh2[og];
            w1 = Wih1[og];
        }
        sm[OFF_B1  + i] = b1;
        sm[OFF_B2  + i] = b2;
        sm[OFF_WI1 + i] = w1;
    }
    if (tid < 52) sm[OFF_WL + tid] = (tid < H_) ? Wlin[tid] : 0.0f;
    if (tid == 0) sm[OFF_BL] = blin[0];
    __syncthreads();

    // warp roles (R6): wid 0..5 = L1 (kh = wid>>1 in 0..2, bh = wid&1)
    //                  wid 6..15 = L2 (kh = (wid-6)>>1 in 0..4, bh = (wid-6)&1)
    const bool isL1 = (wid < 6);
    const int  sub  = isL1 ? wid : wid - 6;
    const int  kh   = sub >> 1;
    const int  bh   = sub & 1;

    const int l1start[4] = {0, 5, 9, 13};
    const int l2start[6] = {0, 6, 11, 16, 21, 26};
    const int kstart = isL1 ? l1start[kh] : l2start[kh];

    const ulonglong2* __restrict__ wp =
        reinterpret_cast<const ulonglong2*>(sm + (isL1 ? OFF_W1 : OFF_W2))
        + kstart * GP_ + lane;
    const ulonglong2* __restrict__ hp =
        reinterpret_cast<const ulonglong2*>(sm + OFF_HS) + bh * 4 * HC + kstart;
    float* pb = sm + (isL1 ? OFF_PB : OFF_PB2) + kh * PR2 + lane;

    const int ub = tid >> 6;              // update batch 0..7
    const int uu = tid & 63;              // update unit
    const bool uact = (uu < H_);

    u64 acc[7][4];

    // ---- prologue: G1(0), U1(0) ----
    if (isL1) {
        if (kh == 0) gate_gemv<5>(wp, hp, acc);
        else         gate_gemv<4>(wp, hp, acc);
        store_partial(pb, sm, lane, bh, acc, kh == 0, sm + OFF_XS + 0 * NB);
    }
    __syncthreads();
    update_l1(sm, ub, uu, uact);
    __syncthreads();

    // ---- pipelined recurrence ----
    for (int t = 0; t < TSTEPS; t++) {
        // phase A: G2(t) on L2 warps; G1(t+1) on L1 warps; out(t-1) on warp 5
        if (isL1) {
            if (t + 1 < TSTEPS) {
                if (kh == 0) gate_gemv<5>(wp, hp, acc);
                else         gate_gemv<4>(wp, hp, acc);
                store_partial(pb, sm, lane, bh, acc, kh == 0,
                              sm + OFF_XS + (t + 1) * NB);
            }
            if (wid == 5 && t > 0) out_phase(sm, lane, bid, t - 1, out);
        } else {
            if (kh == 0) gate_gemv<6>(wp, hp, acc);
            else         gate_gemv<5>(wp, hp, acc);
            store_partial(pb, sm, lane, bh, acc, false, nullptr);
        }
        __syncthreads();

        // phase B: U2(t) + U1(t+1) merged (independent chains, ILP)
        update_both(sm, ub, uu, uact, t + 1 < TSTEPS);
        __syncthreads();
    }

    // ---- epilogue: out(511) ----
    if (wid == 5) out_phase(sm, lane, bid, TSTEPS - 1, out);
}

extern "C" void kernel_launch(void* const* d_in, const int* in_sizes, int n_in,
                              void* d_out, int out_size)
{
    const float* input = (const float*)d_in[0];
    const float* Wih1  = (const float*)d_in[1];
    const float* Whh1  = (const float*)d_in[2];
    const float* bih1  = (const float*)d_in[3];
    const float* bhh1  = (const float*)d_in[4];
    const float* Wih2  = (const float*)d_in[5];
    const float* Whh2  = (const float*)d_in[6];
    const float* bih2  = (const float*)d_in[7];
    const float* bhh2  = (const float*)d_in[8];
    const float* Wlin  = (const float*)d_in[9];
    const float* blin  = (const float*)d_in[10];
    float* out = (float*)d_out;

    static bool attr_set = false;
    if (!attr_set) {
        cudaFuncSetAttribute(lstm_kernel,
                             cudaFuncAttributeMaxDynamicSharedMemorySize,
                             SMEM_BYTES);
        attr_set = true;
    }
    lstm_kernel<<<NBLK, NTHR, SMEM_BYTES>>>(input, Wih1, Whh1, bih1, bhh1,
                                            Wih2, Whh2, bih2, bhh2,
                                            Wlin, blin, out);
}